// round 5
// baseline (speedup 1.0000x reference)
#include <cuda_runtime.h>
#include <cuda_pipeline.h>

#define NROWS 524288
#define DDIM  256
#define NSEG  128
#define TILE_ROWS   32
#define TILE_F4     (TILE_ROWS * DDIM / 4)     // 2048 float4 = 32KB
#define NTILES      (NROWS / TILE_ROWS)        // 16384
#define GRID        444                        // 148 SMs * 3 blocks/SM
#define DYN_SMEM    (2 * TILE_F4 * 16)         // 64KB double buffer

// ---------------- scratch (device globals; no allocation) ----------------
__device__ __align__(16) float g_u[DDIM];   // Wk @ ones
__device__ __align__(16) float g_v[DDIM];   // Wv @ Wo
__device__ float    g_num[NSEG];
__device__ float    g_den[NSEG];
__device__ unsigned g_done;                 // completion ticket

// ---------------- kernel 0: weight collapse + accumulator init ----------------
__global__ void __launch_bounds__(256) prep_kernel(const float* __restrict__ Wk,
                                                   const float* __restrict__ Wv,
                                                   const float* __restrict__ Wo) {
    __shared__ float swo[DDIM];
    int t = threadIdx.x;
    swo[t] = Wo[t];

    if (blockIdx.x == 0) {
        if (t < NSEG) { g_num[t] = 0.0f; g_den[t] = 0.0f; }
        if (t == 128) g_done = 0u;
    }
    __syncthreads();

    int lane = t & 31;
    int warp = t >> 5;
    int d = blockIdx.x * 8 + warp;

    const float4* wk = reinterpret_cast<const float4*>(Wk + (size_t)d * DDIM);
    const float4* wv = reinterpret_cast<const float4*>(Wv + (size_t)d * DDIM);
    const float4* wo = reinterpret_cast<const float4*>(swo);

    float su = 0.0f, sv = 0.0f;
#pragma unroll
    for (int i = 0; i < 2; i++) {
        int idx = lane + 32 * i;
        float4 k = wk[idx];
        float4 v = wv[idx];
        float4 o = wo[idx];
        su += (k.x + k.y) + (k.z + k.w);
        sv += v.x * o.x + v.y * o.y + v.z * o.z + v.w * o.w;
    }
#pragma unroll
    for (int o = 16; o > 0; o >>= 1) {
        su += __shfl_down_sync(0xFFFFFFFFu, su, o);
        sv += __shfl_down_sync(0xFFFFFFFFu, sv, o);
    }
    if (lane == 0) { g_u[d] = su; g_v[d] = sv; }
}

// ---------------- fused persistent kernel with cp.async staging ----------------
// 444 persistent blocks; each grid-strides over 32-row tiles.
// Double-buffered 32KB tiles via cp.async.cg (bypasses L1, no register MLP).
// Compute: 8 lanes per row from shared (each 8-lane phase reads a contiguous
// 128B chunk -> conflict-free), exp + shared-atomic segment accumulation.
__global__ void __launch_bounds__(256) fused_kernel(const float* __restrict__ x,
                                                    const int* __restrict__ seg,
                                                    const float* __restrict__ bv,
                                                    const float* __restrict__ Wo,
                                                    const float* __restrict__ bo,
                                                    float* __restrict__ out) {
    extern __shared__ __align__(16) float4 buf[];   // [2][TILE_F4]
    __shared__ __align__(16) float s_u[DDIM];
    __shared__ __align__(16) float s_v[DDIM];
    __shared__ float s_num[NSEG];
    __shared__ float s_den[NSEG];
    __shared__ bool  s_last;

    int t = threadIdx.x;
    s_u[t] = g_u[t];
    s_v[t] = g_v[t];
    if (t < NSEG) { s_num[t] = 0.0f; s_den[t] = 0.0f; }

    const float4* xv4 = reinterpret_cast<const float4*>(x);
    const float4* su  = reinterpret_cast<const float4*>(s_u);
    const float4* sv  = reinterpret_cast<const float4*>(s_v);

    int lane = t & 31;
    int c    = lane & 7;                    // lane within 8-lane row group
    int g    = (t >> 5) * 4 + (lane >> 3);  // group 0..31 -> row within tile

    // prefetch first tile into buffer 0
    {
        const float4* src = xv4 + (size_t)blockIdx.x * TILE_F4;
#pragma unroll
        for (int i = 0; i < 8; i++)
            __pipeline_memcpy_async(&buf[t + 256 * i], &src[t + 256 * i], 16);
        __pipeline_commit();
    }
    __syncthreads();   // also publishes s_u/s_v/s_num/s_den

    int k = 0;
    for (int tile = blockIdx.x; tile < NTILES; tile += GRID, k++) {
        int nxt = tile + GRID;
        if (nxt < NTILES) {
            float4* dst = buf + ((k + 1) & 1) * TILE_F4;
            const float4* src = xv4 + (size_t)nxt * TILE_F4;
#pragma unroll
            for (int i = 0; i < 8; i++)
                __pipeline_memcpy_async(&dst[t + 256 * i], &src[t + 256 * i], 16);
            __pipeline_commit();
            __pipeline_wait_prior(1);
        } else {
            __pipeline_wait_prior(0);
        }
        __syncthreads();                       // buf[k&1] ready for all threads

        const float4* rp = buf + (k & 1) * TILE_F4 + g * (DDIM / 4);

        float lg0 = 0.0f, lg1 = 0.0f, vl0 = 0.0f, vl1 = 0.0f;
#pragma unroll
        for (int i = 0; i < 8; i += 2) {
            int idx0 = c + 8 * i;
            int idx1 = c + 8 * (i + 1);
            float4 a = rp[idx0], b = rp[idx1];
            float4 ua = su[idx0], ub = su[idx1];
            float4 va = sv[idx0], vb = sv[idx1];
            lg0 = fmaf(a.x, ua.x, lg0); lg0 = fmaf(a.y, ua.y, lg0);
            lg0 = fmaf(a.z, ua.z, lg0); lg0 = fmaf(a.w, ua.w, lg0);
            lg1 = fmaf(b.x, ub.x, lg1); lg1 = fmaf(b.y, ub.y, lg1);
            lg1 = fmaf(b.z, ub.z, lg1); lg1 = fmaf(b.w, ub.w, lg1);
            vl0 = fmaf(a.x, va.x, vl0); vl0 = fmaf(a.y, va.y, vl0);
            vl0 = fmaf(a.z, va.z, vl0); vl0 = fmaf(a.w, va.w, vl0);
            vl1 = fmaf(b.x, vb.x, vl1); vl1 = fmaf(b.y, vb.y, vl1);
            vl1 = fmaf(b.z, vb.z, vl1); vl1 = fmaf(b.w, vb.w, vl1);
        }
        float lg = lg0 + lg1;
        float vl = vl0 + vl1;
#pragma unroll
        for (int o = 4; o > 0; o >>= 1) {
            lg += __shfl_down_sync(0xFFFFFFFFu, lg, o);
            vl += __shfl_down_sync(0xFFFFFFFFu, vl, o);
        }

        if (c == 0) {
            int s = __ldg(&seg[tile * TILE_ROWS + g]);
            float e = __expf(lg);
            atomicAdd(&s_den[s], e);
            atomicAdd(&s_num[s], e * vl);
        }
        __syncthreads();   // compute done before this buffer is overwritten
    }

    // flush block accumulators
    if (t < NSEG && s_den[t] != 0.0f) {
        atomicAdd(&g_num[t], s_num[t]);
        atomicAdd(&g_den[t], s_den[t]);
    }

    // ---- last-block fused finalize ----
    __threadfence();
    __syncthreads();
    if (t == 0) {
        unsigned ticket = atomicAdd(&g_done, 1u);
        s_last = (ticket == (unsigned)(gridDim.x - 1));
    }
    __syncthreads();
    if (!s_last) return;

    __shared__ float s_red[256];
    s_red[t] = bv[t] * Wo[t];
    __syncthreads();
#pragma unroll
    for (int o = 128; o > 0; o >>= 1) {
        if (t < o) s_red[t] += s_red[t + o];
        __syncthreads();
    }
    float c2 = s_red[0];
    float b  = bo[0];
    if (t < NSEG) {
        float den = g_den[t];
        out[t] = (den != 0.0f) ? (g_num[t] / den + c2 + b) : b;
    }
}

// ---------------- launch ----------------
extern "C" void kernel_launch(void* const* d_in, const int* in_sizes, int n_in,
                              void* d_out, int out_size) {
    const float* x   = (const float*)d_in[0];
    const int*   seg = (const int*)d_in[1];
    const float* Wk  = (const float*)d_in[2];
    // d_in[3] = bk (cancels in the segment softmax; unused)
    const float* Wv  = (const float*)d_in[4];
    const float* bv  = (const float*)d_in[5];
    const float* Wo  = (const float*)d_in[6];
    const float* bo  = (const float*)d_in[7];
    float* out = (float*)d_out;

    static int attr_set = 0;
    if (!attr_set) {
        cudaFuncSetAttribute(fused_kernel,
                             cudaFuncAttributeMaxDynamicSharedMemorySize, DYN_SMEM);
        attr_set = 1;
    }

    prep_kernel<<<32, 256>>>(Wk, Wv, Wo);
    fused_kernel<<<GRID, 256, DYN_SMEM>>>(x, seg, bv, Wo, bo, out);
}

// round 6
// speedup vs baseline: 1.5685x; 1.5685x over previous
#include <cuda_runtime.h>

#define NROWS 524288
#define DDIM  256
#define NSEG  128
#define ROWS_PER_BLOCK 64
#define P1_BLOCKS (NROWS / ROWS_PER_BLOCK)   // 8192

// ---------------- scratch (device globals; no allocation) ----------------
__device__ __align__(16) float g_u[DDIM];   // Wk @ ones
__device__ __align__(16) float g_v[DDIM];   // Wv @ Wo
__device__ float    g_num[NSEG];
__device__ float    g_den[NSEG];
__device__ unsigned g_done;                 // completion ticket

// ---------------- kernel 0: weight collapse + accumulator init ----------------
__global__ void __launch_bounds__(256) prep_kernel(const float* __restrict__ Wk,
                                                   const float* __restrict__ Wv,
                                                   const float* __restrict__ Wo) {
    __shared__ float swo[DDIM];
    int t = threadIdx.x;
    swo[t] = Wo[t];

    if (blockIdx.x == 0) {
        if (t < NSEG) { g_num[t] = 0.0f; g_den[t] = 0.0f; }
        if (t == 128) g_done = 0u;
    }
    __syncthreads();

    int lane = t & 31;
    int warp = t >> 5;
    int d = blockIdx.x * 8 + warp;

    const float4* wk = reinterpret_cast<const float4*>(Wk + (size_t)d * DDIM);
    const float4* wv = reinterpret_cast<const float4*>(Wv + (size_t)d * DDIM);
    const float4* wo = reinterpret_cast<const float4*>(swo);

    float su = 0.0f, sv = 0.0f;
#pragma unroll
    for (int i = 0; i < 2; i++) {
        int idx = lane + 32 * i;
        float4 k = wk[idx];
        float4 v = wv[idx];
        float4 o = wo[idx];
        su += (k.x + k.y) + (k.z + k.w);
        sv += v.x * o.x + v.y * o.y + v.z * o.z + v.w * o.w;
    }
#pragma unroll
    for (int o = 16; o > 0; o >>= 1) {
        su += __shfl_down_sync(0xFFFFFFFFu, su, o);
        sv += __shfl_down_sync(0xFFFFFFFFu, sv, o);
    }
    if (lane == 0) { g_u[d] = su; g_v[d] = sv; }
}

// ---------------- fused kernel ----------------
// 16 lanes per row, 4 float4 chunks per thread, 2 rows per warp per pass,
// 64 rows per block (grid 8192). launch_bounds(256,7): <=36 regs ->
// 7 blocks/SM -> 56/64 warps (87.5% occ).
__global__ void __launch_bounds__(256, 7) fused_kernel(const float* __restrict__ x,
                                                       const int* __restrict__ seg,
                                                       const float* __restrict__ bv,
                                                       const float* __restrict__ Wo,
                                                       const float* __restrict__ bo,
                                                       float* __restrict__ out) {
    __shared__ __align__(16) float s_u[DDIM];
    __shared__ __align__(16) float s_v[DDIM];
    __shared__ float s_num[NSEG];
    __shared__ float s_den[NSEG];
    __shared__ bool  s_last;

    int t = threadIdx.x;
    s_u[t] = g_u[t];
    s_v[t] = g_v[t];
    if (t < NSEG) { s_num[t] = 0.0f; s_den[t] = 0.0f; }
    __syncthreads();

    int lane = t & 31;
    int c    = lane & 15;                    // lane within 16-lane row group
    int warp = t >> 5;
    int g    = (warp << 1) | (lane >> 4);    // group 0..15 within block

    const float4* su = reinterpret_cast<const float4*>(s_u);
    const float4* sv = reinterpret_cast<const float4*>(s_v);

    float accN = 0.0f, accD = 0.0f;
    int curSeg = -1;

#pragma unroll 1
    for (int r = 0; r < 4; r++) {
        int row = blockIdx.x * ROWS_PER_BLOCK + r * 16 + g;
        const float4* xp = reinterpret_cast<const float4*>(x + (size_t)row * DDIM);

        // 4 independent streaming loads (MLP=4/thread, 8 LDG.128/warp in flight)
        float4 x0 = __ldcs(&xp[c]);
        float4 x1 = __ldcs(&xp[c + 16]);
        float4 x2 = __ldcs(&xp[c + 32]);
        float4 x3 = __ldcs(&xp[c + 48]);

        float lg = 0.0f, vl = 0.0f;
        {
            float4 u0 = su[c],      v0 = sv[c];
            lg = fmaf(x0.x, u0.x, lg); lg = fmaf(x0.y, u0.y, lg);
            lg = fmaf(x0.z, u0.z, lg); lg = fmaf(x0.w, u0.w, lg);
            vl = fmaf(x0.x, v0.x, vl); vl = fmaf(x0.y, v0.y, vl);
            vl = fmaf(x0.z, v0.z, vl); vl = fmaf(x0.w, v0.w, vl);
        }
        {
            float4 u1 = su[c + 16], v1 = sv[c + 16];
            lg = fmaf(x1.x, u1.x, lg); lg = fmaf(x1.y, u1.y, lg);
            lg = fmaf(x1.z, u1.z, lg); lg = fmaf(x1.w, u1.w, lg);
            vl = fmaf(x1.x, v1.x, vl); vl = fmaf(x1.y, v1.y, vl);
            vl = fmaf(x1.z, v1.z, vl); vl = fmaf(x1.w, v1.w, vl);
        }
        {
            float4 u2 = su[c + 32], v2 = sv[c + 32];
            lg = fmaf(x2.x, u2.x, lg); lg = fmaf(x2.y, u2.y, lg);
            lg = fmaf(x2.z, u2.z, lg); lg = fmaf(x2.w, u2.w, lg);
            vl = fmaf(x2.x, v2.x, vl); vl = fmaf(x2.y, v2.y, vl);
            vl = fmaf(x2.z, v2.z, vl); vl = fmaf(x2.w, v2.w, vl);
        }
        {
            float4 u3 = su[c + 48], v3 = sv[c + 48];
            lg = fmaf(x3.x, u3.x, lg); lg = fmaf(x3.y, u3.y, lg);
            lg = fmaf(x3.z, u3.z, lg); lg = fmaf(x3.w, u3.w, lg);
            vl = fmaf(x3.x, v3.x, vl); vl = fmaf(x3.y, v3.y, vl);
            vl = fmaf(x3.z, v3.z, vl); vl = fmaf(x3.w, v3.w, vl);
        }

#pragma unroll
        for (int o = 8; o > 0; o >>= 1) {
            lg += __shfl_down_sync(0xFFFFFFFFu, lg, o);
            vl += __shfl_down_sync(0xFFFFFFFFu, vl, o);
        }

        if (c == 0) {
            int s = __ldg(&seg[row]);
            if (s != curSeg) {               // sorted segments: rare
                if (curSeg >= 0) {
                    atomicAdd(&s_num[curSeg], accN);
                    atomicAdd(&s_den[curSeg], accD);
                }
                curSeg = s; accN = 0.0f; accD = 0.0f;
            }
            float e = __expf(lg);
            accD += e;
            accN = fmaf(e, vl, accN);
        }
    }
    if (c == 0 && curSeg >= 0) {
        atomicAdd(&s_num[curSeg], accN);
        atomicAdd(&s_den[curSeg], accD);
    }

    __syncthreads();
    if (t < NSEG && s_den[t] != 0.0f) {
        atomicAdd(&g_num[t], s_num[t]);
        atomicAdd(&g_den[t], s_den[t]);
    }

    // ---- last-block fused finalize ----
    __threadfence();
    __syncthreads();
    if (t == 0) {
        unsigned ticket = atomicAdd(&g_done, 1u);
        s_last = (ticket == (unsigned)(gridDim.x - 1));
    }
    __syncthreads();
    if (!s_last) return;

    __shared__ float s_red[256];
    s_red[t] = bv[t] * Wo[t];
    __syncthreads();
#pragma unroll
    for (int o = 128; o > 0; o >>= 1) {
        if (t < o) s_red[t] += s_red[t + o];
        __syncthreads();
    }
    float c2 = s_red[0];
    float b  = bo[0];
    if (t < NSEG) {
        float den = g_den[t];
        out[t] = (den != 0.0f) ? (g_num[t] / den + c2 + b) : b;
    }
}

// ---------------- launch ----------------
extern "C" void kernel_launch(void* const* d_in, const int* in_sizes, int n_in,
                              void* d_out, int out_size) {
    const float* x   = (const float*)d_in[0];
    const int*   seg = (const int*)d_in[1];
    const float* Wk  = (const float*)d_in[2];
    // d_in[3] = bk (cancels in the segment softmax; unused)
    const float* Wv  = (const float*)d_in[4];
    const float* bv  = (const float*)d_in[5];
    const float* Wo  = (const float*)d_in[6];
    const float* bo  = (const float*)d_in[7];
    float* out = (float*)d_out;

    prep_kernel<<<32, 256>>>(Wk, Wv, Wo);
    fused_kernel<<<P1_BLOCKS, 256>>>(x, seg, bv, Wo, bo, out);
}